// round 15
// baseline (speedup 1.0000x reference)
#include <cuda_runtime.h>

#define NPTS 120000
#define INC  256
#define MIDC 64
#define OUTC 256
#define KNB  27
#define EPSV 1e-5f

typedef unsigned long long u64;
typedef unsigned int u32;

// ---- f32x2 packed helpers ----
__device__ __forceinline__ u64 pk2(float a) {
    u64 r; asm("mov.b64 %0,{%1,%1};" : "=l"(r) : "f"(a)); return r;
}
__device__ __forceinline__ void fma2(u64& d, u64 a, u64 b) {
    asm("fma.rn.f32x2 %0,%1,%2,%0;" : "+l"(d) : "l"(a), "l"(b));
}
__device__ __forceinline__ float2 up2(u64 v) {
    float2 r; asm("mov.b64 {%0,%1},%2;" : "=f"(r.x), "=f"(r.y) : "l"(v)); return r;
}

// ---- cp.async ----
__device__ __forceinline__ u32 sptr(const void* p) { return (u32)__cvta_generic_to_shared(p); }
__device__ __forceinline__ void cpa16(u32 d, const void* s) {
    asm volatile("cp.async.ca.shared.global [%0],[%1],16;" :: "r"(d), "l"(s));
}
__device__ __forceinline__ void cpa_commit() { asm volatile("cp.async.commit_group;"); }
template<int N> __device__ __forceinline__ void cpa_wait() {
    asm volatile("cp.async.wait_group %0;" :: "n"(N));
}

// ---------------- scratch ----------------
__device__ float g_h1[(size_t)NPTS * MIDC];
__device__ float g_r1[(size_t)NPTS * MIDC];
__device__ float g_h2[(size_t)NPTS * MIDC];
__device__ float g_h3[(size_t)NPTS * OUTC];
__device__ float g_sum1[MIDC], g_ssq1[MIDC], g_a1[MIDC], g_c1[MIDC];
__device__ float g_sum2[MIDC], g_ssq2[MIDC], g_a2[MIDC], g_c2[MIDC];
__device__ float g_sum3[OUTC], g_ssq3[OUTC], g_a3[OUTC], g_c3[OUTC];

__global__ void k_zero() {
    int t = threadIdx.x;
    if (t < MIDC) { g_sum1[t] = 0.f; g_ssq1[t] = 0.f; g_sum2[t] = 0.f; g_ssq2[t] = 0.f; }
    g_sum3[t] = 0.f; g_ssq3[t] = 0.f;
}

// stats over a 128x64 block tile; 512 threads, each holds outf[4][4] (zeros for invalid rows)
__device__ __forceinline__ void block_stats4(float outf[4][4], float* s0, float* s1,
                                             int tid, int col0,
                                             float* gsum, float* gssq, int colbase) {
    float s[4] = {}, q[4] = {};
#pragma unroll
    for (int i = 0; i < 4; i++)
#pragma unroll
        for (int j = 0; j < 4; j++) { float v = outf[i][j]; s[j] += v; q[j] += v * v; }
    __syncthreads();
    int rg = tid >> 4;   // 0..31 row-groups
#pragma unroll
    for (int j = 0; j < 4; j++) {
        s0[rg * 64 + col0 + j] = s[j];
        s1[rg * 64 + col0 + j] = q[j];
    }
    __syncthreads();
    if (tid < 64) {
        float S = 0.f, Q = 0.f;
#pragma unroll
        for (int g = 0; g < 32; g++) { S += s0[g * 64 + tid]; Q += s1[g * 64 + tid]; }
        atomicAdd(&gsum[colbase + tid], S);
        atomicAdd(&gssq[colbase + tid], Q);
    }
}

// 128x64 += 128x64 @ 64x64, stride-64 smem tiles; 4 rows per thread (512-thread CTA)
__device__ __forceinline__ void mm_tile64(const float* As, const float* Bs,
                                          int row0, int col0, u64 acc[4][2]) {
#pragma unroll 8
    for (int kk = 0; kk < 64; kk += 2) {
        ulonglong2 bv0 = *(const ulonglong2*)&Bs[kk * 64 + col0];
        ulonglong2 bv1 = *(const ulonglong2*)&Bs[(kk + 1) * 64 + col0];
#pragma unroll
        for (int i = 0; i < 4; i++) {
            float2 a = *(const float2*)&As[(row0 + i) * 64 + kk];
            u64 a0 = pk2(a.x), a1 = pk2(a.y);
            fma2(acc[i][0], a0, bv0.x);
            fma2(acc[i][1], a0, bv0.y);
            fma2(acc[i][0], a1, bv1.x);
            fma2(acc[i][1], a1, bv1.y);
        }
    }
}

// ---------------- GEMM1: g_h1 = x @ W1; cp.async pipelined; fused stats ----------------
__global__ __launch_bounds__(512) void k_gemm1(const float* __restrict__ x,
                                               const float* __restrict__ W1) {
    extern __shared__ float smem[];
    float* As = smem;                 // 2 * 128*64
    float* Bs = smem + 2 * 128 * 64;  // 2 * 64*64
    const int tid  = threadIdx.x;
    const int p0   = blockIdx.x * 128;
    const int nval = (NPTS - p0 < 128) ? (NPTS - p0) : 128;
    const int row0 = (tid >> 4) << 2;
    const int col0 = (tid & 15) << 2;
    u64 acc[4][2] = {};

    auto issue = [&](int kc, int buf) {
        float* Ad = As + buf * 8192;
        float* Bd = Bs + buf * 4096;
#pragma unroll
        for (int i = 0; i < 4; i++) {
            int j4 = tid + i * 512;
            int r = j4 >> 4, c = (j4 & 15) << 2;
            int re = (r < nval) ? r : 0;
            cpa16(sptr(&Ad[r * 64 + c]), x + (size_t)(p0 + re) * INC + kc * 64 + c);
        }
#pragma unroll
        for (int i = 0; i < 2; i++) {
            int j4 = tid + i * 512;
            int r = j4 >> 4, c = (j4 & 15) << 2;
            cpa16(sptr(&Bd[r * 64 + c]), W1 + (size_t)(kc * 64 + r) * MIDC + c);
        }
        cpa_commit();
    };

    issue(0, 0);
    for (int kc = 0; kc < 4; kc++) {
        int cur = kc & 1;
        if (kc + 1 < 4) { issue(kc + 1, cur ^ 1); cpa_wait<1>(); }
        else cpa_wait<0>();
        __syncthreads();
        mm_tile64(As + cur * 8192, Bs + cur * 4096, row0, col0, acc);
        __syncthreads();
    }

    float outf[4][4];
#pragma unroll
    for (int i = 0; i < 4; i++) {
        float2 p = up2(acc[i][0]), q = up2(acc[i][1]);
        bool v = (row0 + i) < nval;
        outf[i][0] = v ? p.x : 0.f; outf[i][1] = v ? p.y : 0.f;
        outf[i][2] = v ? q.x : 0.f; outf[i][3] = v ? q.y : 0.f;
        if (v)
            *(float4*)&g_h1[(size_t)(p0 + row0 + i) * MIDC + col0] =
                make_float4(p.x, p.y, q.x, q.y);
    }
    block_stats4(outf, As, Bs, tid, col0, g_sum1, g_ssq1, 0);
}

// ---------------- BN finalize ----------------
__global__ void k_finalize(const float* __restrict__ g, const float* __restrict__ b, int which) {
    int i = threadIdx.x;
    int C = (which == 2) ? OUTC : MIDC;
    if (i >= C) return;
    const float* sum = (which == 0) ? g_sum1 : (which == 1) ? g_sum2 : g_sum3;
    const float* ssq = (which == 0) ? g_ssq1 : (which == 1) ? g_ssq2 : g_ssq3;
    float* a = (which == 0) ? g_a1 : (which == 1) ? g_a2 : g_a3;
    float* c = (which == 0) ? g_c1 : (which == 1) ? g_c2 : g_c3;
    float m = sum[i] * (1.f / NPTS);
    float v = ssq[i] * (1.f / NPTS) - m * m;
    float ai = g[i] * rsqrtf(v + EPSV);
    a[i] = ai;
    c[i] = b[i] - m * ai;
}

// ---------------- norm1: g_r1 = relu(bn1(g_h1)) ----------------
__global__ __launch_bounds__(256) void k_norm1() {
    const size_t total4 = (size_t)NPTS * MIDC / 4;
    for (size_t i4 = (size_t)blockIdx.x * blockDim.x + threadIdx.x; i4 < total4;
         i4 += (size_t)gridDim.x * blockDim.x) {
        int c = (int)((i4 * 4) & (MIDC - 1));
        float4 v = *(const float4*)&g_h1[i4 * 4];
        v.x = fmaxf(fmaf(v.x, g_a1[c + 0], g_c1[c + 0]), 0.f);
        v.y = fmaxf(fmaf(v.y, g_a1[c + 1], g_c1[c + 1]), 0.f);
        v.z = fmaxf(fmaf(v.z, g_a1[c + 2], g_c1[c + 2]), 0.f);
        v.w = fmaxf(fmaf(v.w, g_a1[c + 3], g_c1[c + 3]), 0.f);
        *(float4*)&g_r1[i4 * 4] = v;
    }
}

// ---------------- gather GEMM (cp.async pipelined) + fused stats ----------------
__global__ __launch_bounds__(512) void k_gather(const int* __restrict__ nbr,
                                                const float* __restrict__ W3) {
    extern __shared__ float smem[];
    float* As = smem;                      // 2 * 128*64
    float* Bs = smem + 2 * 128 * 64;       // 2 * 64*64
    int*   sidx = (int*)(smem + 2 * 128 * 64 + 2 * 64 * 64); // 128*KNB
    const int tid = threadIdx.x;
    const int p0  = blockIdx.x * 128;
    const int nval = (NPTS - p0 < 128) ? (NPTS - p0) : 128;
    const int row0 = (tid >> 4) << 2;
    const int col0 = (tid & 15) << 2;

    for (int i = tid; i < nval * KNB; i += 512) sidx[i] = nbr[(size_t)p0 * KNB + i];
    __syncthreads();

    auto issue = [&](int k, int buf) {
        float* Bd = Bs + buf * 4096;
        const float* wb = W3 + (size_t)k * MIDC * MIDC;
#pragma unroll
        for (int i = 0; i < 2; i++) {
            int j4 = tid + i * 512;
            int r = j4 >> 4, c = (j4 & 15) << 2;
            cpa16(sptr(&Bd[r * 64 + c]), wb + r * 64 + c);
        }
        float* Ad = As + buf * 8192;
#pragma unroll
        for (int i = 0; i < 4; i++) {
            int j4 = tid + i * 512;
            int r = j4 >> 4, c = (j4 & 15) << 2;
            int ridx = (r < nval) ? sidx[r * KNB + k] : 0;
            cpa16(sptr(&Ad[r * 64 + c]), g_r1 + (size_t)ridx * MIDC + c);
        }
        cpa_commit();
    };

    u64 acc[4][2] = {};
    issue(0, 0);
    for (int k = 0; k < KNB; k++) {
        int cur = k & 1;
        if (k + 1 < KNB) { issue(k + 1, cur ^ 1); cpa_wait<1>(); }
        else cpa_wait<0>();
        __syncthreads();
        mm_tile64(As + cur * 8192, Bs + cur * 4096, row0, col0, acc);
        __syncthreads();
    }

    float outf[4][4];
#pragma unroll
    for (int i = 0; i < 4; i++) {
        float2 p = up2(acc[i][0]), q = up2(acc[i][1]);
        bool v = (row0 + i) < nval;
        outf[i][0] = v ? p.x : 0.f; outf[i][1] = v ? p.y : 0.f;
        outf[i][2] = v ? q.x : 0.f; outf[i][3] = v ? q.y : 0.f;
        if (v)
            *(float4*)&g_h2[(size_t)(p0 + row0 + i) * MIDC + col0] =
                make_float4(p.x, p.y, q.x, q.y);
    }
    block_stats4(outf, As, Bs, tid, col0, g_sum2, g_ssq2, 0);
}

// ---------------- GEMM2: g_h3 = relu(bn2(g_h2)) @ W2; fused stats ----------------
__global__ __launch_bounds__(512) void k_gemm2(const float* __restrict__ W2) {
    extern __shared__ float smem[];
    float* As = smem;             // 128*64
    float* Bs = smem + 128 * 64;  // 64*64
    float* sa = smem + 192 * 64;
    float* sc = sa + MIDC;
    const int tid = threadIdx.x;
    const int p0  = blockIdx.x * 128;
    const int cb  = blockIdx.y * 64;
    const int nval = (NPTS - p0 < 128) ? (NPTS - p0) : 128;
    if (tid < MIDC) { sa[tid] = g_a2[tid]; sc[tid] = g_c2[tid]; }
    __syncthreads();
#pragma unroll
    for (int i = 0; i < 4; i++) {
        int j4 = tid + i * 512;
        int r = j4 >> 4, c = (j4 & 15) << 2;
        int re = (r < nval) ? r : 0;
        float4 v = *(const float4*)&g_h2[(size_t)(p0 + re) * MIDC + c];
        v.x = fmaxf(fmaf(v.x, sa[c + 0], sc[c + 0]), 0.f);
        v.y = fmaxf(fmaf(v.y, sa[c + 1], sc[c + 1]), 0.f);
        v.z = fmaxf(fmaf(v.z, sa[c + 2], sc[c + 2]), 0.f);
        v.w = fmaxf(fmaf(v.w, sa[c + 3], sc[c + 3]), 0.f);
        *(float4*)&As[r * 64 + c] = v;
    }
#pragma unroll
    for (int i = 0; i < 2; i++) {
        int j4 = tid + i * 512;
        int r = j4 >> 4, c = (j4 & 15) << 2;
        *(float4*)&Bs[r * 64 + c] = *(const float4*)(W2 + (size_t)r * OUTC + cb + c);
    }
    __syncthreads();
    const int row0 = (tid >> 4) << 2;
    const int col0 = (tid & 15) << 2;
    u64 acc[4][2] = {};
    mm_tile64(As, Bs, row0, col0, acc);

    float outf[4][4];
#pragma unroll
    for (int i = 0; i < 4; i++) {
        float2 p = up2(acc[i][0]), q = up2(acc[i][1]);
        bool v = (row0 + i) < nval;
        outf[i][0] = v ? p.x : 0.f; outf[i][1] = v ? p.y : 0.f;
        outf[i][2] = v ? q.x : 0.f; outf[i][3] = v ? q.y : 0.f;
        if (v)
            *(float4*)&g_h3[(size_t)(p0 + row0 + i) * OUTC + cb + col0] =
                make_float4(p.x, p.y, q.x, q.y);
    }
    block_stats4(outf, As, Bs, tid, col0, g_sum3, g_ssq3, cb);
}

// ---------------- epilogue: out = relu(bn3(h3) + x) ----------------
__global__ __launch_bounds__(256) void k_out(const float* __restrict__ x,
                                             float* __restrict__ out) {
    const size_t total4 = (size_t)NPTS * OUTC / 4;
    for (size_t i4 = (size_t)blockIdx.x * blockDim.x + threadIdx.x; i4 < total4;
         i4 += (size_t)gridDim.x * blockDim.x) {
        int c = (int)((i4 * 4) & (OUTC - 1));
        float4 h  = *(const float4*)&g_h3[i4 * 4];
        float4 xv = ((const float4*)x)[i4];
        float4 o;
        o.x = fmaxf(fmaf(h.x, g_a3[c + 0], g_c3[c + 0]) + xv.x, 0.f);
        o.y = fmaxf(fmaf(h.y, g_a3[c + 1], g_c3[c + 1]) + xv.y, 0.f);
        o.z = fmaxf(fmaf(h.z, g_a3[c + 2], g_c3[c + 2]) + xv.z, 0.f);
        o.w = fmaxf(fmaf(h.w, g_a3[c + 3], g_c3[c + 3]) + xv.w, 0.f);
        ((float4*)out)[i4] = o;
    }
}

// ---------------- launch ----------------
extern "C" void kernel_launch(void* const* d_in, const int* in_sizes, int n_in,
                              void* d_out, int out_size) {
    const float* x   = (const float*)d_in[0];
    const int*   nbr = (const int*)d_in[1];
    const float* W1  = (const float*)d_in[2];
    const float* W3  = (const float*)d_in[3];
    const float* W2  = (const float*)d_in[4];
    const float* g1  = (const float*)d_in[5];
    const float* b1  = (const float*)d_in[6];
    const float* g2  = (const float*)d_in[7];
    const float* b2  = (const float*)d_in[8];
    const float* g3  = (const float*)d_in[9];
    const float* b3  = (const float*)d_in[10];
    float* out = (float*)d_out;

    const int SM_G1  = (2 * 128 * 64 + 2 * 64 * 64) * 4;                  // 96 KB
    const int SM_GAT = SM_G1 + 128 * KNB * 4;                             // ~109.5 KB
    const int SM_G2  = (128 * 64 + 64 * 64) * 4 + 2 * MIDC * 4;           // ~48.5 KB
    static bool attr_done = false;
    if (!attr_done) {
        cudaFuncSetAttribute(k_gemm1, cudaFuncAttributeMaxDynamicSharedMemorySize, SM_G1);
        cudaFuncSetAttribute(k_gather, cudaFuncAttributeMaxDynamicSharedMemorySize, SM_GAT);
        cudaFuncSetAttribute(k_gemm2, cudaFuncAttributeMaxDynamicSharedMemorySize, SM_G2);
        attr_done = true;
    }

    const int GB = (NPTS + 127) / 128;  // 938
    k_zero<<<1, 256>>>();
    k_gemm1<<<GB, 512, SM_G1>>>(x, W1);
    k_finalize<<<1, 256>>>(g1, b1, 0);
    k_norm1<<<2048, 256>>>();
    k_gather<<<GB, 512, SM_GAT>>>(nbr, W3);
    k_finalize<<<1, 256>>>(g2, b2, 1);
    dim3 grid2(GB, 4);
    k_gemm2<<<grid2, 512, SM_G2>>>(W2);
    k_finalize<<<1, 256>>>(g3, b3, 2);
    k_out<<<2048, 256>>>(x, out);
}

// round 16
// speedup vs baseline: 1.1031x; 1.1031x over previous
#include <cuda_runtime.h>

#define NPTS 120000
#define INC  256
#define MIDC 64
#define OUTC 256
#define KNB  27
#define EPSV 1e-5f

typedef unsigned long long u64;
typedef unsigned int u32;

// ---- f32x2 packed helpers ----
__device__ __forceinline__ u64 pk2(float a) {
    u64 r; asm("mov.b64 %0,{%1,%1};" : "=l"(r) : "f"(a)); return r;
}
__device__ __forceinline__ void fma2(u64& d, u64 a, u64 b) {
    asm("fma.rn.f32x2 %0,%1,%2,%0;" : "+l"(d) : "l"(a), "l"(b));
}
__device__ __forceinline__ float2 up2(u64 v) {
    float2 r; asm("mov.b64 {%0,%1},%2;" : "=f"(r.x), "=f"(r.y) : "l"(v)); return r;
}

// ---- cp.async ----
__device__ __forceinline__ u32 sptr(const void* p) { return (u32)__cvta_generic_to_shared(p); }
__device__ __forceinline__ void cpa16(u32 d, const void* s) {
    asm volatile("cp.async.ca.shared.global [%0],[%1],16;" :: "r"(d), "l"(s));
}
__device__ __forceinline__ void cpa_commit() { asm volatile("cp.async.commit_group;"); }
template<int N> __device__ __forceinline__ void cpa_wait() {
    asm volatile("cp.async.wait_group %0;" :: "n"(N));
}

// ---------------- scratch ----------------
__device__ float g_h1[(size_t)NPTS * MIDC];
__device__ float g_r1[(size_t)NPTS * MIDC];
__device__ float g_h2[(size_t)NPTS * MIDC];
__device__ float g_h3[(size_t)NPTS * OUTC];
__device__ float g_sum1[MIDC], g_ssq1[MIDC], g_a1[MIDC], g_c1[MIDC];
__device__ float g_sum2[MIDC], g_ssq2[MIDC], g_a2[MIDC], g_c2[MIDC];
__device__ float g_sum3[OUTC], g_ssq3[OUTC], g_a3[OUTC], g_c3[OUTC];

__global__ void k_zero() {
    int t = threadIdx.x;
    if (t < MIDC) { g_sum1[t] = 0.f; g_ssq1[t] = 0.f; g_sum2[t] = 0.f; g_ssq2[t] = 0.f; }
    g_sum3[t] = 0.f; g_ssq3[t] = 0.f;
}

// stats over a block tile; NG row-groups (16 for 256thr, 32 for 512thr), outf[8][4] per thread
template<int NG>
__device__ __forceinline__ void block_stats8(float outf[8][4], float* s0, float* s1,
                                             int tid, int col0,
                                             float* gsum, float* gssq, int colbase) {
    float s[4] = {}, q[4] = {};
#pragma unroll
    for (int i = 0; i < 8; i++)
#pragma unroll
        for (int j = 0; j < 4; j++) { float v = outf[i][j]; s[j] += v; q[j] += v * v; }
    __syncthreads();
    int rg = tid >> 4;
#pragma unroll
    for (int j = 0; j < 4; j++) {
        s0[rg * 64 + col0 + j] = s[j];
        s1[rg * 64 + col0 + j] = q[j];
    }
    __syncthreads();
    if (tid < 64) {
        float S = 0.f, Q = 0.f;
#pragma unroll
        for (int g = 0; g < NG; g++) { S += s0[g * 64 + tid]; Q += s1[g * 64 + tid]; }
        atomicAdd(&gsum[colbase + tid], S);
        atomicAdd(&gssq[colbase + tid], Q);
    }
}

// (rows x 64) += (rows x 64) @ 64x64, stride-64 smem tiles; 8 rows x 4 cols per thread
__device__ __forceinline__ void mm_tile64(const float* As, const float* Bs,
                                          int row0, int col0, u64 acc[8][2]) {
#pragma unroll 8
    for (int kk = 0; kk < 64; kk += 2) {
        ulonglong2 bv0 = *(const ulonglong2*)&Bs[kk * 64 + col0];
        ulonglong2 bv1 = *(const ulonglong2*)&Bs[(kk + 1) * 64 + col0];
#pragma unroll
        for (int i = 0; i < 8; i++) {
            float2 a = *(const float2*)&As[(row0 + i) * 64 + kk];
            u64 a0 = pk2(a.x), a1 = pk2(a.y);
            fma2(acc[i][0], a0, bv0.x);
            fma2(acc[i][1], a0, bv0.y);
            fma2(acc[i][0], a1, bv1.x);
            fma2(acc[i][1], a1, bv1.y);
        }
    }
}

// ---------------- GEMM1: g_h1 = x @ W1; cp.async pipelined; fused stats (256 thr) ----------------
__global__ __launch_bounds__(256) void k_gemm1(const float* __restrict__ x,
                                               const float* __restrict__ W1) {
    extern __shared__ float smem[];
    float* As = smem;                 // 2 * 128*64
    float* Bs = smem + 2 * 128 * 64;  // 2 * 64*64
    const int tid  = threadIdx.x;
    const int p0   = blockIdx.x * 128;
    const int nval = (NPTS - p0 < 128) ? (NPTS - p0) : 128;
    const int row0 = (tid >> 4) << 3;
    const int col0 = (tid & 15) << 2;
    u64 acc[8][2] = {};

    auto issue = [&](int kc, int buf) {
        float* Ad = As + buf * 8192;
        float* Bd = Bs + buf * 4096;
#pragma unroll
        for (int i = 0; i < 8; i++) {
            int j4 = tid + i * 256;
            int r = j4 >> 4, c = (j4 & 15) << 2;
            int re = (r < nval) ? r : 0;
            cpa16(sptr(&Ad[r * 64 + c]), x + (size_t)(p0 + re) * INC + kc * 64 + c);
        }
#pragma unroll
        for (int i = 0; i < 4; i++) {
            int j4 = tid + i * 256;
            int r = j4 >> 4, c = (j4 & 15) << 2;
            cpa16(sptr(&Bd[r * 64 + c]), W1 + (size_t)(kc * 64 + r) * MIDC + c);
        }
        cpa_commit();
    };

    issue(0, 0);
    for (int kc = 0; kc < 4; kc++) {
        int cur = kc & 1;
        if (kc + 1 < 4) { issue(kc + 1, cur ^ 1); cpa_wait<1>(); }
        else cpa_wait<0>();
        __syncthreads();
        mm_tile64(As + cur * 8192, Bs + cur * 4096, row0, col0, acc);
        __syncthreads();
    }

    float outf[8][4];
#pragma unroll
    for (int i = 0; i < 8; i++) {
        float2 p = up2(acc[i][0]), q = up2(acc[i][1]);
        bool v = (row0 + i) < nval;
        outf[i][0] = v ? p.x : 0.f; outf[i][1] = v ? p.y : 0.f;
        outf[i][2] = v ? q.x : 0.f; outf[i][3] = v ? q.y : 0.f;
        if (v)
            *(float4*)&g_h1[(size_t)(p0 + row0 + i) * MIDC + col0] =
                make_float4(p.x, p.y, q.x, q.y);
    }
    block_stats8<16>(outf, As, Bs, tid, col0, g_sum1, g_ssq1, 0);
}

// ---------------- BN finalize ----------------
__global__ void k_finalize(const float* __restrict__ g, const float* __restrict__ b, int which) {
    int i = threadIdx.x;
    int C = (which == 2) ? OUTC : MIDC;
    if (i >= C) return;
    const float* sum = (which == 0) ? g_sum1 : (which == 1) ? g_sum2 : g_sum3;
    const float* ssq = (which == 0) ? g_ssq1 : (which == 1) ? g_ssq2 : g_ssq3;
    float* a = (which == 0) ? g_a1 : (which == 1) ? g_a2 : g_a3;
    float* c = (which == 0) ? g_c1 : (which == 1) ? g_c2 : g_c3;
    float m = sum[i] * (1.f / NPTS);
    float v = ssq[i] * (1.f / NPTS) - m * m;
    float ai = g[i] * rsqrtf(v + EPSV);
    a[i] = ai;
    c[i] = b[i] - m * ai;
}

// ---------------- norm1: g_r1 = relu(bn1(g_h1)) ----------------
__global__ __launch_bounds__(256) void k_norm1() {
    const size_t total4 = (size_t)NPTS * MIDC / 4;
    for (size_t i4 = (size_t)blockIdx.x * blockDim.x + threadIdx.x; i4 < total4;
         i4 += (size_t)gridDim.x * blockDim.x) {
        int c = (int)((i4 * 4) & (MIDC - 1));
        float4 v = *(const float4*)&g_h1[i4 * 4];
        v.x = fmaxf(fmaf(v.x, g_a1[c + 0], g_c1[c + 0]), 0.f);
        v.y = fmaxf(fmaf(v.y, g_a1[c + 1], g_c1[c + 1]), 0.f);
        v.z = fmaxf(fmaf(v.z, g_a1[c + 2], g_c1[c + 2]), 0.f);
        v.w = fmaxf(fmaf(v.w, g_a1[c + 3], g_c1[c + 3]), 0.f);
        *(float4*)&g_r1[i4 * 4] = v;
    }
}

// ---------------- gather GEMM: 256x64 tiles, 512 threads (halves B re-staging) ----------------
// smem floats: A 2*(256*64) = 32768, B 2*(64*64) = 8192, sidx 256*27 ints
#define GAT_AFL (256 * 64)
#define GAT_SMEM ((2 * GAT_AFL + 2 * 64 * 64) * 4 + 256 * KNB * 4)   // ~187 KB

__global__ __launch_bounds__(512) void k_gather(const int* __restrict__ nbr,
                                                const float* __restrict__ W3) {
    extern __shared__ float smem[];
    float* As = smem;                        // 2 * 256*64
    float* Bs = smem + 2 * GAT_AFL;          // 2 * 64*64
    int*   sidx = (int*)(Bs + 2 * 64 * 64);  // 256*KNB
    const int tid = threadIdx.x;
    const int p0  = blockIdx.x * 256;
    const int nval = (NPTS - p0 < 256) ? (NPTS - p0) : 256;
    const int row0 = (tid >> 4) << 3;        // 0..248 step 8
    const int col0 = (tid & 15) << 2;

    for (int i = tid; i < nval * KNB; i += 512) sidx[i] = nbr[(size_t)p0 * KNB + i];
    __syncthreads();

    auto issue = [&](int k, int buf) {
        float* Bd = Bs + buf * 4096;
        const float* wb = W3 + (size_t)k * MIDC * MIDC;
#pragma unroll
        for (int i = 0; i < 2; i++) {
            int j4 = tid + i * 512;
            int r = j4 >> 4, c = (j4 & 15) << 2;
            cpa16(sptr(&Bd[r * 64 + c]), wb + r * 64 + c);
        }
        float* Ad = As + buf * GAT_AFL;
#pragma unroll
        for (int i = 0; i < 8; i++) {
            int j4 = tid + i * 512;
            int r = j4 >> 4, c = (j4 & 15) << 2;
            int ridx = (r < nval) ? sidx[r * KNB + k] : 0;
            cpa16(sptr(&Ad[r * 64 + c]), g_r1 + (size_t)ridx * MIDC + c);
        }
        cpa_commit();
    };

    u64 acc[8][2] = {};
    issue(0, 0);
    for (int k = 0; k < KNB; k++) {
        int cur = k & 1;
        if (k + 1 < KNB) { issue(k + 1, cur ^ 1); cpa_wait<1>(); }
        else cpa_wait<0>();
        __syncthreads();
        mm_tile64(As + cur * GAT_AFL, Bs + cur * 4096, row0, col0, acc);
        __syncthreads();
    }

    float outf[8][4];
#pragma unroll
    for (int i = 0; i < 8; i++) {
        float2 p = up2(acc[i][0]), q = up2(acc[i][1]);
        bool v = (row0 + i) < nval;
        outf[i][0] = v ? p.x : 0.f; outf[i][1] = v ? p.y : 0.f;
        outf[i][2] = v ? q.x : 0.f; outf[i][3] = v ? q.y : 0.f;
        if (v)
            *(float4*)&g_h2[(size_t)(p0 + row0 + i) * MIDC + col0] =
                make_float4(p.x, p.y, q.x, q.y);
    }
    block_stats8<32>(outf, As, Bs, tid, col0, g_sum2, g_ssq2, 0);
}

// ---------------- GEMM2: g_h3 = relu(bn2(g_h2)) @ W2; fused stats (256 thr) ----------------
__global__ __launch_bounds__(256) void k_gemm2(const float* __restrict__ W2) {
    extern __shared__ float smem[];
    float* As = smem;             // 128*64
    float* Bs = smem + 128 * 64;  // 64*64
    float* sa = smem + 192 * 64;
    float* sc = sa + MIDC;
    const int tid = threadIdx.x;
    const int p0  = blockIdx.x * 128;
    const int cb  = blockIdx.y * 64;
    const int nval = (NPTS - p0 < 128) ? (NPTS - p0) : 128;
    if (tid < MIDC) { sa[tid] = g_a2[tid]; sc[tid] = g_c2[tid]; }
    __syncthreads();
#pragma unroll
    for (int i = 0; i < 8; i++) {
        int j4 = tid + i * 256;
        int r = j4 >> 4, c = (j4 & 15) << 2;
        int re = (r < nval) ? r : 0;
        float4 v = *(const float4*)&g_h2[(size_t)(p0 + re) * MIDC + c];
        v.x = fmaxf(fmaf(v.x, sa[c + 0], sc[c + 0]), 0.f);
        v.y = fmaxf(fmaf(v.y, sa[c + 1], sc[c + 1]), 0.f);
        v.z = fmaxf(fmaf(v.z, sa[c + 2], sc[c + 2]), 0.f);
        v.w = fmaxf(fmaf(v.w, sa[c + 3], sc[c + 3]), 0.f);
        *(float4*)&As[r * 64 + c] = v;
    }
#pragma unroll
    for (int i = 0; i < 4; i++) {
        int j4 = tid + i * 256;
        int r = j4 >> 4, c = (j4 & 15) << 2;
        *(float4*)&Bs[r * 64 + c] = *(const float4*)(W2 + (size_t)r * OUTC + cb + c);
    }
    __syncthreads();
    const int row0 = (tid >> 4) << 3;
    const int col0 = (tid & 15) << 2;
    u64 acc[8][2] = {};
    mm_tile64(As, Bs, row0, col0, acc);

    float outf[8][4];
#pragma unroll
    for (int i = 0; i < 8; i++) {
        float2 p = up2(acc[i][0]), q = up2(acc[i][1]);
        bool v = (row0 + i) < nval;
        outf[i][0] = v ? p.x : 0.f; outf[i][1] = v ? p.y : 0.f;
        outf[i][2] = v ? q.x : 0.f; outf[i][3] = v ? q.y : 0.f;
        if (v)
            *(float4*)&g_h3[(size_t)(p0 + row0 + i) * OUTC + cb + col0] =
                make_float4(p.x, p.y, q.x, q.y);
    }
    block_stats8<16>(outf, As, Bs, tid, col0, g_sum3, g_ssq3, cb);
}

// ---------------- epilogue: out = relu(bn3(h3) + x) ----------------
__global__ __launch_bounds__(256) void k_out(const float* __restrict__ x,
                                             float* __restrict__ out) {
    const size_t total4 = (size_t)NPTS * OUTC / 4;
    for (size_t i4 = (size_t)blockIdx.x * blockDim.x + threadIdx.x; i4 < total4;
         i4 += (size_t)gridDim.x * blockDim.x) {
        int c = (int)((i4 * 4) & (OUTC - 1));
        float4 h  = *(const float4*)&g_h3[i4 * 4];
        float4 xv = ((const float4*)x)[i4];
        float4 o;
        o.x = fmaxf(fmaf(h.x, g_a3[c + 0], g_c3[c + 0]) + xv.x, 0.f);
        o.y = fmaxf(fmaf(h.y, g_a3[c + 1], g_c3[c + 1]) + xv.y, 0.f);
        o.z = fmaxf(fmaf(h.z, g_a3[c + 2], g_c3[c + 2]) + xv.z, 0.f);
        o.w = fmaxf(fmaf(h.w, g_a3[c + 3], g_c3[c + 3]) + xv.w, 0.f);
        ((float4*)out)[i4] = o;
    }
}

// ---------------- launch ----------------
extern "C" void kernel_launch(void* const* d_in, const int* in_sizes, int n_in,
                              void* d_out, int out_size) {
    const float* x   = (const float*)d_in[0];
    const int*   nbr = (const int*)d_in[1];
    const float* W1  = (const float*)d_in[2];
    const float* W3  = (const float*)d_in[3];
    const float* W2  = (const float*)d_in[4];
    const float* g1  = (const float*)d_in[5];
    const float* b1  = (const float*)d_in[6];
    const float* g2  = (const float*)d_in[7];
    const float* b2  = (const float*)d_in[8];
    const float* g3  = (const float*)d_in[9];
    const float* b3  = (const float*)d_in[10];
    float* out = (float*)d_out;

    const int SM_G1  = (2 * 128 * 64 + 2 * 64 * 64) * 4;                  // 96 KB
    const int SM_G2  = (128 * 64 + 64 * 64) * 4 + 2 * MIDC * 4;           // ~48.5 KB
    static bool attr_done = false;
    if (!attr_done) {
        cudaFuncSetAttribute(k_gemm1, cudaFuncAttributeMaxDynamicSharedMemorySize, SM_G1);
        cudaFuncSetAttribute(k_gather, cudaFuncAttributeMaxDynamicSharedMemorySize, GAT_SMEM);
        cudaFuncSetAttribute(k_gemm2, cudaFuncAttributeMaxDynamicSharedMemorySize, SM_G2);
        attr_done = true;
    }

    const int GB128 = (NPTS + 127) / 128;  // 938
    const int GB256 = (NPTS + 255) / 256;  // 469
    k_zero<<<1, 256>>>();
    k_gemm1<<<GB128, 256, SM_G1>>>(x, W1);
    k_finalize<<<1, 256>>>(g1, b1, 0);
    k_norm1<<<2048, 256>>>();
    k_gather<<<GB256, 512, GAT_SMEM>>>(nbr, W3);
    k_finalize<<<1, 256>>>(g2, b2, 1);
    dim3 grid2(GB128, 4);
    k_gemm2<<<grid2, 256, SM_G2>>>(W2);
    k_finalize<<<1, 256>>>(g3, b3, 2);
    k_out<<<2048, 256>>>(x, out);
}